// round 9
// baseline (speedup 1.0000x reference)
#include <cuda_runtime.h>

// Problem constants
// cos_similar: (4, 1024, 32, 32) fp32
// b:           (4, 32, 256, 256) fp32
// mask:        (4, 1, 256, 256)  fp32
// out:         (4, 32, 256, 256) fp32
//
// Reformulation:
//   W[b,c,Y,X] = bpad[b,c,Y,X] * (1 - mpad[b,0,Y,X]),  (replicate pad 4, 264x264)
//   out[b,c,8u+i0-4,8v+j0-4] = sum_{Y',X' in [0,33)} W[b,c,8Y'+i0,8X'+j0] * T[b,Y',X',u,v]
//   T[b,Y',X',u,v] = sum_{di,dj in {0,1}} cos[b,(Y'-di)*32+(X'-dj), u-di, v-dj]  (guarded)
// => per-batch GEMM: A[M=2048, K=1089] x T[K=1089, N=1089]

constexpr int MDIM = 2048;   // (i0*8+j0)*32 + c
constexpr int KDIM = 1089;   // Y'*33 + X'
constexpr int NDIM = 1089;   // u*33 + v
constexpr int KPAD = 1120;   // multiple of 32 (and of BK)
constexpr int NPAD = 1152;   // 9 * 128

__device__ float g_A[4 * MDIM * KPAD];   // ~36.7 MB
__device__ float g_T[4 * KPAD * NPAD];   // ~20.6 MB

// ---------------------------------------------------------------------------
// Build A: A[b][m][k] = W[b,c, 8Y'+i0, 8X'+j0], m=(i0*8+j0)*32+c, k=Y'*33+X'
// ---------------------------------------------------------------------------
__global__ void build_A_kernel(const float* __restrict__ bsrc,
                               const float* __restrict__ mask) {
    int idx = blockIdx.x * blockDim.x + threadIdx.x;
    constexpr int total = 4 * MDIM * KPAD;
    if (idx >= total) return;
    int k = idx % KPAD;
    int t = idx / KPAD;
    int m = t % MDIM;
    int b = t / MDIM;
    float val = 0.f;
    if (k < KDIM) {
        int Yp = k / 33, Xp = k - Yp * 33;
        int c  = m & 31;
        int j0 = (m >> 5) & 7;
        int i0 = m >> 8;
        int Y = 8 * Yp + i0 - 4;           // unpadded row
        int X = 8 * Xp + j0 - 4;
        Y = min(max(Y, 0), 255);           // replicate padding
        X = min(max(X, 0), 255);
        float bv = bsrc[(((size_t)b * 32 + c) * 256 + Y) * 256 + X];
        float mv = mask[((size_t)b * 256 + Y) * 256 + X];
        val = bv * (1.f - mv);
    }
    g_A[idx] = val;
}

// ---------------------------------------------------------------------------
// Build T: T[b][k][n], k=Y'*33+X', n=u*33+v
// ---------------------------------------------------------------------------
__global__ void build_T_kernel(const float* __restrict__ cosv) {
    int idx = blockIdx.x * blockDim.x + threadIdx.x;
    constexpr int total = 4 * KPAD * NPAD;
    if (idx >= total) return;
    int n = idx % NPAD;
    int t = idx / NPAD;
    int k = t % KPAD;
    int b = t / KPAD;
    float val = 0.f;
    if (k < KDIM && n < NDIM) {
        int Yp = k / 33, Xp = k - Yp * 33;
        int u  = n / 33, v  = n - u * 33;
        const float* cb = cosv + (size_t)b * (1024 * 32 * 32);
        #pragma unroll
        for (int di = 0; di < 2; di++) {
            bool okY = di ? (Yp >= 1 && u >= 1) : (Yp < 32 && u < 32);
            if (!okY) continue;
            #pragma unroll
            for (int dj = 0; dj < 2; dj++) {
                bool okX = dj ? (Xp >= 1 && v >= 1) : (Xp < 32 && v < 32);
                if (!okX) continue;
                int l = (Yp - di) * 32 + (Xp - dj);
                val += cb[(l * 32 + (u - di)) * 32 + (v - dj)];
            }
        }
    }
    g_T[idx] = val;
}

// ---------------------------------------------------------------------------
// SGEMM: per batch b, C[m,n] = sum_k A[m,k] * T[k,n], fused scatter epilogue.
// BM=BN=128, BK=8, 256 threads, 8x8 per-thread tile, smem double-buffered.
// ---------------------------------------------------------------------------
constexpr int BM = 128, BN = 128, BK = 8, TM = 8, TN = 8;

__global__ __launch_bounds__(256, 2) void gemm_kernel(float* __restrict__ out) {
    int b  = blockIdx.z;
    int m0 = blockIdx.y * BM;
    int n0 = blockIdx.x * BN;
    const float* A  = g_A + (size_t)b * MDIM * KPAD;
    const float* Bm = g_T + (size_t)b * KPAD * NPAD;

    __shared__ float As[2][BK][BM];
    __shared__ float Bs[2][BK][BN];

    int tid  = threadIdx.x;
    int rowA = tid >> 1;           // 0..127
    int colA = (tid & 1) * 4;      // 0 or 4
    int rowB = tid >> 5;           // 0..7
    int colB = (tid & 31) * 4;     // 0..124
    int tx   = tid & 15;
    int ty   = tid >> 4;

    float acc[TM][TN] = {};

    // prologue: stage 0
    {
        float4 a4 = *(const float4*)(A + (size_t)(m0 + rowA) * KPAD + colA);
        float4 b4 = *(const float4*)(Bm + (size_t)rowB * NPAD + n0 + colB);
        As[0][colA + 0][rowA] = a4.x;
        As[0][colA + 1][rowA] = a4.y;
        As[0][colA + 2][rowA] = a4.z;
        As[0][colA + 3][rowA] = a4.w;
        *(float4*)(&Bs[0][rowB][colB]) = b4;
    }
    __syncthreads();

    constexpr int NK = KPAD / BK;  // 140
    for (int kt = 0; kt < NK; kt++) {
        int cur = kt & 1;
        float4 a4n, b4n;
        if (kt + 1 < NK) {
            a4n = *(const float4*)(A + (size_t)(m0 + rowA) * KPAD + (kt + 1) * BK + colA);
            b4n = *(const float4*)(Bm + (size_t)((kt + 1) * BK + rowB) * NPAD + n0 + colB);
        }
        #pragma unroll
        for (int kk = 0; kk < BK; kk++) {
            float4 a0  = *(const float4*)&As[cur][kk][ty * TM];
            float4 a1  = *(const float4*)&As[cur][kk][ty * TM + 4];
            float4 bb0 = *(const float4*)&Bs[cur][kk][tx * TN];
            float4 bb1 = *(const float4*)&Bs[cur][kk][tx * TN + 4];
            float ar[8] = {a0.x, a0.y, a0.z, a0.w, a1.x, a1.y, a1.z, a1.w};
            float br[8] = {bb0.x, bb0.y, bb0.z, bb0.w, bb1.x, bb1.y, bb1.z, bb1.w};
            #pragma unroll
            for (int i = 0; i < TM; i++)
                #pragma unroll
                for (int j = 0; j < TN; j++)
                    acc[i][j] += ar[i] * br[j];
        }
        if (kt + 1 < NK) {
            int nxt = cur ^ 1;
            As[nxt][colA + 0][rowA] = a4n.x;
            As[nxt][colA + 1][rowA] = a4n.y;
            As[nxt][colA + 2][rowA] = a4n.z;
            As[nxt][colA + 3][rowA] = a4n.w;
            *(float4*)(&Bs[nxt][rowB][colB]) = b4n;
            __syncthreads();
        }
    }

    // Epilogue: scatter C[m,n] -> out[b, c, 8u+i0-4, 8v+j0-4] (crop guard)
    float* outp = out + (size_t)b * 32 * 256 * 256;
    int uu[TN], vv[TN];
    bool nok[TN];
    #pragma unroll
    for (int j = 0; j < TN; j++) {
        int n = n0 + tx * TN + j;
        nok[j] = (n < NDIM);
        int u = n / 33;
        uu[j] = u;
        vv[j] = n - u * 33;
    }
    #pragma unroll
    for (int i = 0; i < TM; i++) {
        int m  = m0 + ty * TM + i;
        int c  = m & 31;
        int j0 = (m >> 5) & 7;
        int i0 = m >> 8;
        #pragma unroll
        for (int j = 0; j < TN; j++) {
            if (!nok[j]) continue;
            int y = 8 * uu[j] + i0 - 4;
            int x = 8 * vv[j] + j0 - 4;
            if ((unsigned)y < 256u && (unsigned)x < 256u)
                outp[((size_t)c * 256 + y) * 256 + x] = acc[i][j];
        }
    }
}

// ---------------------------------------------------------------------------
extern "C" void kernel_launch(void* const* d_in, const int* in_sizes, int n_in,
                              void* d_out, int out_size) {
    const float* cosv = (const float*)d_in[0];   // (4,1024,32,32)
    const float* bsrc = (const float*)d_in[1];   // (4,32,256,256)
    const float* mask = (const float*)d_in[2];   // (4,1,256,256)
    float* out = (float*)d_out;                  // (4,32,256,256)

    {
        constexpr int total = 4 * MDIM * KPAD;
        build_A_kernel<<<(total + 255) / 256, 256>>>(bsrc, mask);
    }
    {
        constexpr int total = 4 * KPAD * NPAD;
        build_T_kernel<<<(total + 255) / 256, 256>>>(cosv);
    }
    dim3 grid(NPAD / BN, MDIM / BM, 4);   // (9, 16, 4)
    gemm_kernel<<<grid, 256>>>(out);
}

// round 10
// speedup vs baseline: 1.0032x; 1.0032x over previous
#include <cuda_runtime.h>

// Problem constants
// cos_similar: (4, 1024, 32, 32) fp32
// b:           (4, 32, 256, 256) fp32
// mask:        (4, 1, 256, 256)  fp32
// out:         (4, 32, 256, 256) fp32
//
// Reformulation:
//   W[b,c,Y,X] = bpad[b,c,Y,X] * (1 - mpad[b,0,Y,X]),  (replicate pad 4, 264x264)
//   out[b,c,8u+i0-4,8v+j0-4] = sum_{Y',X' in [0,33)} W[b,c,8Y'+i0,8X'+j0] * T[b,Y',X',u,v]
//   T[b,Y',X',u,v] = sum_{di,dj in {0,1}} cos[b,(Y'-di)*32+(X'-dj), u-di, v-dj]  (guarded)
// => per-batch GEMM: A[M=2048, K=1089] x T[K=1089, N=1089]

constexpr int MDIM = 2048;   // (i0*8+j0)*32 + c
constexpr int KDIM = 1089;   // Y'*33 + X'
constexpr int NDIM = 1089;   // u*33 + v
constexpr int KPAD = 1120;   // multiple of 32 (and of BK)
constexpr int NPAD = 1152;   // 9 * 128

__device__ float g_A[4 * MDIM * KPAD];   // ~36.7 MB
__device__ float g_T[4 * KPAD * NPAD];   // ~20.6 MB

// ---------------------------------------------------------------------------
// Build A: A[b][m][k] = W[b,c, 8Y'+i0, 8X'+j0], m=(i0*8+j0)*32+c, k=Y'*33+X'
// ---------------------------------------------------------------------------
__global__ void build_A_kernel(const float* __restrict__ bsrc,
                               const float* __restrict__ mask) {
    int idx = blockIdx.x * blockDim.x + threadIdx.x;
    constexpr int total = 4 * MDIM * KPAD;
    if (idx >= total) return;
    int k = idx % KPAD;
    int t = idx / KPAD;
    int m = t % MDIM;
    int b = t / MDIM;
    float val = 0.f;
    if (k < KDIM) {
        int Yp = k / 33, Xp = k - Yp * 33;
        int c  = m & 31;
        int j0 = (m >> 5) & 7;
        int i0 = m >> 8;
        int Y = 8 * Yp + i0 - 4;           // unpadded row
        int X = 8 * Xp + j0 - 4;
        Y = min(max(Y, 0), 255);           // replicate padding
        X = min(max(X, 0), 255);
        float bv = bsrc[(((size_t)b * 32 + c) * 256 + Y) * 256 + X];
        float mv = mask[((size_t)b * 256 + Y) * 256 + X];
        val = bv * (1.f - mv);
    }
    g_A[idx] = val;
}

// ---------------------------------------------------------------------------
// Build T: T[b][k][n], k=Y'*33+X', n=u*33+v
// ---------------------------------------------------------------------------
__global__ void build_T_kernel(const float* __restrict__ cosv) {
    int idx = blockIdx.x * blockDim.x + threadIdx.x;
    constexpr int total = 4 * KPAD * NPAD;
    if (idx >= total) return;
    int n = idx % NPAD;
    int t = idx / NPAD;
    int k = t % KPAD;
    int b = t / KPAD;
    float val = 0.f;
    if (k < KDIM && n < NDIM) {
        int Yp = k / 33, Xp = k - Yp * 33;
        int u  = n / 33, v  = n - u * 33;
        const float* cb = cosv + (size_t)b * (1024 * 32 * 32);
        #pragma unroll
        for (int di = 0; di < 2; di++) {
            bool okY = di ? (Yp >= 1 && u >= 1) : (Yp < 32 && u < 32);
            if (!okY) continue;
            #pragma unroll
            for (int dj = 0; dj < 2; dj++) {
                bool okX = dj ? (Xp >= 1 && v >= 1) : (Xp < 32 && v < 32);
                if (!okX) continue;
                int l = (Yp - di) * 32 + (Xp - dj);
                val += cb[(l * 32 + (u - di)) * 32 + (v - dj)];
            }
        }
    }
    g_T[idx] = val;
}

// ---------------------------------------------------------------------------
// SGEMM: per batch b, C[m,n] = sum_k A[m,k] * T[k,n], fused scatter epilogue.
// BM=BN=128, BK=8, 256 threads, 8x8 per-thread tile, smem double-buffered.
// ---------------------------------------------------------------------------
constexpr int BM = 128, BN = 128, BK = 8, TM = 8, TN = 8;

__global__ __launch_bounds__(256, 2) void gemm_kernel(float* __restrict__ out) {
    int b  = blockIdx.z;
    int m0 = blockIdx.y * BM;
    int n0 = blockIdx.x * BN;
    const float* A  = g_A + (size_t)b * MDIM * KPAD;
    const float* Bm = g_T + (size_t)b * KPAD * NPAD;

    __shared__ float As[2][BK][BM];
    __shared__ float Bs[2][BK][BN];

    int tid  = threadIdx.x;
    int rowA = tid >> 1;           // 0..127
    int colA = (tid & 1) * 4;      // 0 or 4
    int rowB = tid >> 5;           // 0..7
    int colB = (tid & 31) * 4;     // 0..124
    int tx   = tid & 15;
    int ty   = tid >> 4;

    float acc[TM][TN] = {};

    // prologue: stage 0
    {
        float4 a4 = *(const float4*)(A + (size_t)(m0 + rowA) * KPAD + colA);
        float4 b4 = *(const float4*)(Bm + (size_t)rowB * NPAD + n0 + colB);
        As[0][colA + 0][rowA] = a4.x;
        As[0][colA + 1][rowA] = a4.y;
        As[0][colA + 2][rowA] = a4.z;
        As[0][colA + 3][rowA] = a4.w;
        *(float4*)(&Bs[0][rowB][colB]) = b4;
    }
    __syncthreads();

    constexpr int NK = KPAD / BK;  // 140
    for (int kt = 0; kt < NK; kt++) {
        int cur = kt & 1;
        float4 a4n, b4n;
        if (kt + 1 < NK) {
            a4n = *(const float4*)(A + (size_t)(m0 + rowA) * KPAD + (kt + 1) * BK + colA);
            b4n = *(const float4*)(Bm + (size_t)((kt + 1) * BK + rowB) * NPAD + n0 + colB);
        }
        #pragma unroll
        for (int kk = 0; kk < BK; kk++) {
            float4 a0  = *(const float4*)&As[cur][kk][ty * TM];
            float4 a1  = *(const float4*)&As[cur][kk][ty * TM + 4];
            float4 bb0 = *(const float4*)&Bs[cur][kk][tx * TN];
            float4 bb1 = *(const float4*)&Bs[cur][kk][tx * TN + 4];
            float ar[8] = {a0.x, a0.y, a0.z, a0.w, a1.x, a1.y, a1.z, a1.w};
            float br[8] = {bb0.x, bb0.y, bb0.z, bb0.w, bb1.x, bb1.y, bb1.z, bb1.w};
            #pragma unroll
            for (int i = 0; i < TM; i++)
                #pragma unroll
                for (int j = 0; j < TN; j++)
                    acc[i][j] += ar[i] * br[j];
        }
        if (kt + 1 < NK) {
            int nxt = cur ^ 1;
            As[nxt][colA + 0][rowA] = a4n.x;
            As[nxt][colA + 1][rowA] = a4n.y;
            As[nxt][colA + 2][rowA] = a4n.z;
            As[nxt][colA + 3][rowA] = a4n.w;
            *(float4*)(&Bs[nxt][rowB][colB]) = b4n;
            __syncthreads();
        }
    }

    // Epilogue: scatter C[m,n] -> out[b, c, 8u+i0-4, 8v+j0-4] (crop guard)
    float* outp = out + (size_t)b * 32 * 256 * 256;
    int uu[TN], vv[TN];
    bool nok[TN];
    #pragma unroll
    for (int j = 0; j < TN; j++) {
        int n = n0 + tx * TN + j;
        nok[j] = (n < NDIM);
        int u = n / 33;
        uu[j] = u;
        vv[j] = n - u * 33;
    }
    #pragma unroll
    for (int i = 0; i < TM; i++) {
        int m  = m0 + ty * TM + i;
        int c  = m & 31;
        int j0 = (m >> 5) & 7;
        int i0 = m >> 8;
        #pragma unroll
        for (int j = 0; j < TN; j++) {
            if (!nok[j]) continue;
            int y = 8 * uu[j] + i0 - 4;
            int x = 8 * vv[j] + j0 - 4;
            if ((unsigned)y < 256u && (unsigned)x < 256u)
                outp[((size_t)c * 256 + y) * 256 + x] = acc[i][j];
        }
    }
}

// ---------------------------------------------------------------------------
extern "C" void kernel_launch(void* const* d_in, const int* in_sizes, int n_in,
                              void* d_out, int out_size) {
    const float* cosv = (const float*)d_in[0];   // (4,1024,32,32)
    const float* bsrc = (const float*)d_in[1];   // (4,32,256,256)
    const float* mask = (const float*)d_in[2];   // (4,1,256,256)
    float* out = (float*)d_out;                  // (4,32,256,256)

    {
        constexpr int total = 4 * MDIM * KPAD;
        build_A_kernel<<<(total + 255) / 256, 256>>>(bsrc, mask);
    }
    {
        constexpr int total = 4 * KPAD * NPAD;
        build_T_kernel<<<(total + 255) / 256, 256>>>(cosv);
    }
    dim3 grid(NPAD / BN, MDIM / BM, 4);   // (9, 16, 4)
    gemm_kernel<<<grid, 256>>>(out);
}

// round 11
// speedup vs baseline: 1.0059x; 1.0027x over previous
#include <cuda_runtime.h>

// Problem constants
// cos_similar: (4, 1024, 32, 32) fp32
// b:           (4, 32, 256, 256) fp32
// mask:        (4, 1, 256, 256)  fp32
// out:         (4, 32, 256, 256) fp32
//
// Reformulation:
//   W[b,c,Y,X] = bpad[b,c,Y,X] * (1 - mpad[b,0,Y,X]),  (replicate pad 4, 264x264)
//   out[b,c,8u+i0-4,8v+j0-4] = sum_{Y',X' in [0,33)} W[b,c,8Y'+i0,8X'+j0] * T[b,Y',X',u,v]
//   T[b,Y',X',u,v] = sum_{di,dj in {0,1}} cos[b,(Y'-di)*32+(X'-dj), u-di, v-dj]  (guarded)
// => per-batch GEMM: A[M=2048, K=1089] x T[K=1089, N=1089]

constexpr int MDIM = 2048;   // (i0*8+j0)*32 + c
constexpr int KDIM = 1089;   // Y'*33 + X'
constexpr int NDIM = 1089;   // u*33 + v
constexpr int KPAD = 1120;   // multiple of 32 (and of BK)
constexpr int NPAD = 1152;   // 9 * 128

__device__ float g_A[4 * MDIM * KPAD];   // ~36.7 MB
__device__ float g_T[4 * KPAD * NPAD];   // ~20.6 MB

// ---------------------------------------------------------------------------
// Build A: A[b][m][k] = W[b,c, 8Y'+i0, 8X'+j0], m=(i0*8+j0)*32+c, k=Y'*33+X'
// ---------------------------------------------------------------------------
__global__ void build_A_kernel(const float* __restrict__ bsrc,
                               const float* __restrict__ mask) {
    int idx = blockIdx.x * blockDim.x + threadIdx.x;
    constexpr int total = 4 * MDIM * KPAD;
    if (idx >= total) return;
    int k = idx % KPAD;
    int t = idx / KPAD;
    int m = t % MDIM;
    int b = t / MDIM;
    float val = 0.f;
    if (k < KDIM) {
        int Yp = k / 33, Xp = k - Yp * 33;
        int c  = m & 31;
        int j0 = (m >> 5) & 7;
        int i0 = m >> 8;
        int Y = 8 * Yp + i0 - 4;           // unpadded row
        int X = 8 * Xp + j0 - 4;
        Y = min(max(Y, 0), 255);           // replicate padding
        X = min(max(X, 0), 255);
        float bv = bsrc[(((size_t)b * 32 + c) * 256 + Y) * 256 + X];
        float mv = mask[((size_t)b * 256 + Y) * 256 + X];
        val = bv * (1.f - mv);
    }
    g_A[idx] = val;
}

// ---------------------------------------------------------------------------
// Build T: T[b][k][n], k=Y'*33+X', n=u*33+v
// ---------------------------------------------------------------------------
__global__ void build_T_kernel(const float* __restrict__ cosv) {
    int idx = blockIdx.x * blockDim.x + threadIdx.x;
    constexpr int total = 4 * KPAD * NPAD;
    if (idx >= total) return;
    int n = idx % NPAD;
    int t = idx / NPAD;
    int k = t % KPAD;
    int b = t / KPAD;
    float val = 0.f;
    if (k < KDIM && n < NDIM) {
        int Yp = k / 33, Xp = k - Yp * 33;
        int u  = n / 33, v  = n - u * 33;
        const float* cb = cosv + (size_t)b * (1024 * 32 * 32);
        #pragma unroll
        for (int di = 0; di < 2; di++) {
            bool okY = di ? (Yp >= 1 && u >= 1) : (Yp < 32 && u < 32);
            if (!okY) continue;
            #pragma unroll
            for (int dj = 0; dj < 2; dj++) {
                bool okX = dj ? (Xp >= 1 && v >= 1) : (Xp < 32 && v < 32);
                if (!okX) continue;
                int l = (Yp - di) * 32 + (Xp - dj);
                val += cb[(l * 32 + (u - di)) * 32 + (v - dj)];
            }
        }
    }
    g_T[idx] = val;
}

// ---------------------------------------------------------------------------
// SGEMM: per batch b, C[m,n] = sum_k A[m,k] * T[k,n], fused scatter epilogue.
// BM=BN=128, BK=8, 256 threads, 8x8 per-thread tile, smem double-buffered.
// ---------------------------------------------------------------------------
constexpr int BM = 128, BN = 128, BK = 8, TM = 8, TN = 8;

__global__ __launch_bounds__(256, 2) void gemm_kernel(float* __restrict__ out) {
    int b  = blockIdx.z;
    int m0 = blockIdx.y * BM;
    int n0 = blockIdx.x * BN;
    const float* A  = g_A + (size_t)b * MDIM * KPAD;
    const float* Bm = g_T + (size_t)b * KPAD * NPAD;

    __shared__ float As[2][BK][BM];
    __shared__ float Bs[2][BK][BN];

    int tid  = threadIdx.x;
    int rowA = tid >> 1;           // 0..127
    int colA = (tid & 1) * 4;      // 0 or 4
    int rowB = tid >> 5;           // 0..7
    int colB = (tid & 31) * 4;     // 0..124
    int tx   = tid & 15;
    int ty   = tid >> 4;

    float acc[TM][TN] = {};

    // prologue: stage 0
    {
        float4 a4 = *(const float4*)(A + (size_t)(m0 + rowA) * KPAD + colA);
        float4 b4 = *(const float4*)(Bm + (size_t)rowB * NPAD + n0 + colB);
        As[0][colA + 0][rowA] = a4.x;
        As[0][colA + 1][rowA] = a4.y;
        As[0][colA + 2][rowA] = a4.z;
        As[0][colA + 3][rowA] = a4.w;
        *(float4*)(&Bs[0][rowB][colB]) = b4;
    }
    __syncthreads();

    constexpr int NK = KPAD / BK;  // 140
    for (int kt = 0; kt < NK; kt++) {
        int cur = kt & 1;
        float4 a4n, b4n;
        if (kt + 1 < NK) {
            a4n = *(const float4*)(A + (size_t)(m0 + rowA) * KPAD + (kt + 1) * BK + colA);
            b4n = *(const float4*)(Bm + (size_t)((kt + 1) * BK + rowB) * NPAD + n0 + colB);
        }
        #pragma unroll
        for (int kk = 0; kk < BK; kk++) {
            float4 a0  = *(const float4*)&As[cur][kk][ty * TM];
            float4 a1  = *(const float4*)&As[cur][kk][ty * TM + 4];
            float4 bb0 = *(const float4*)&Bs[cur][kk][tx * TN];
            float4 bb1 = *(const float4*)&Bs[cur][kk][tx * TN + 4];
            float ar[8] = {a0.x, a0.y, a0.z, a0.w, a1.x, a1.y, a1.z, a1.w};
            float br[8] = {bb0.x, bb0.y, bb0.z, bb0.w, bb1.x, bb1.y, bb1.z, bb1.w};
            #pragma unroll
            for (int i = 0; i < TM; i++)
                #pragma unroll
                for (int j = 0; j < TN; j++)
                    acc[i][j] += ar[i] * br[j];
        }
        if (kt + 1 < NK) {
            int nxt = cur ^ 1;
            As[nxt][colA + 0][rowA] = a4n.x;
            As[nxt][colA + 1][rowA] = a4n.y;
            As[nxt][colA + 2][rowA] = a4n.z;
            As[nxt][colA + 3][rowA] = a4n.w;
            *(float4*)(&Bs[nxt][rowB][colB]) = b4n;
            __syncthreads();
        }
    }

    // Epilogue: scatter C[m,n] -> out[b, c, 8u+i0-4, 8v+j0-4] (crop guard)
    float* outp = out + (size_t)b * 32 * 256 * 256;
    int uu[TN], vv[TN];
    bool nok[TN];
    #pragma unroll
    for (int j = 0; j < TN; j++) {
        int n = n0 + tx * TN + j;
        nok[j] = (n < NDIM);
        int u = n / 33;
        uu[j] = u;
        vv[j] = n - u * 33;
    }
    #pragma unroll
    for (int i = 0; i < TM; i++) {
        int m  = m0 + ty * TM + i;
        int c  = m & 31;
        int j0 = (m >> 5) & 7;
        int i0 = m >> 8;
        #pragma unroll
        for (int j = 0; j < TN; j++) {
            if (!nok[j]) continue;
            int y = 8 * uu[j] + i0 - 4;
            int x = 8 * vv[j] + j0 - 4;
            if ((unsigned)y < 256u && (unsigned)x < 256u)
                outp[((size_t)c * 256 + y) * 256 + x] = acc[i][j];
        }
    }
}

// ---------------------------------------------------------------------------
extern "C" void kernel_launch(void* const* d_in, const int* in_sizes, int n_in,
                              void* d_out, int out_size) {
    const float* cosv = (const float*)d_in[0];   // (4,1024,32,32)
    const float* bsrc = (const float*)d_in[1];   // (4,32,256,256)
    const float* mask = (const float*)d_in[2];   // (4,1,256,256)
    float* out = (float*)d_out;                  // (4,32,256,256)

    {
        constexpr int total = 4 * MDIM * KPAD;
        build_A_kernel<<<(total + 255) / 256, 256>>>(bsrc, mask);
    }
    {
        constexpr int total = 4 * KPAD * NPAD;
        build_T_kernel<<<(total + 255) / 256, 256>>>(cosv);
    }
    dim3 grid(NPAD / BN, MDIM / BM, 4);   // (9, 16, 4)
    gemm_kernel<<<grid, 256>>>(out);
}